// round 15
// baseline (speedup 1.0000x reference)
#include <cuda_runtime.h>
#include <cuda_bf16.h>
#include <math.h>

#define BB 64
#define SS 1024
#define II 256
#define HH 512
#define OO 256
#define G4 2048
#define NCTA 128          // 64 groups x 2 (k-split pair)
#define NGRP 64

// step smem map (bytes); pitch-528 rows
#define XPITCH 528
#define SM_WHI 0
#define SM_WLO 16896
#define SM_HHI 33792
#define SM_HLO 67584
#define SM_TOTAL 101376
#define GBP 66            // gbuf: 128 rows x 66 fl = 33792 B, aliases SM_HHI

// precompute2 smem map (R12, unchanged)
#define PC_A_HI 0
#define PC_A_LO 33792
#define PC_B_HI 67584
#define PC_B_LO 101376
#define PC_TOTAL 135168
#define RP 66
#define RSLAB 4224

#define FLAG_PAD 32

__device__ __forceinline__ float fsigmoid(float x){ return __fdividef(1.0f, 1.0f + __expf(-x)); }
__device__ __forceinline__ float ftanh(float x){ return 1.0f - 2.0f*__fdividef(1.0f, __expf(2.0f*x)+1.0f); }
__device__ __forceinline__ unsigned smem_u32(const void* p) {
    unsigned a;
    asm("{.reg .u64 t; cvta.to.shared.u64 t, %1; cvt.u32.u64 %0, t;}" : "=r"(a) : "l"(p));
    return a;
}
__device__ __forceinline__ void ldsm4(unsigned* r, unsigned addr) {
    asm volatile("ldmatrix.sync.aligned.m8n8.x4.shared.b16 {%0,%1,%2,%3}, [%4];"
                 : "=r"(r[0]), "=r"(r[1]), "=r"(r[2]), "=r"(r[3]) : "r"(addr));
}
__device__ __forceinline__ void mma16816(float* c, const unsigned* a, unsigned b0, unsigned b1) {
    asm volatile(
        "mma.sync.aligned.m16n8k16.row.col.f32.bf16.bf16.f32 "
        "{%0,%1,%2,%3},{%4,%5,%6,%7},{%8,%9},{%0,%1,%2,%3};"
        : "+f"(c[0]), "+f"(c[1]), "+f"(c[2]), "+f"(c[3])
        : "r"(a[0]), "r"(a[1]), "r"(a[2]), "r"(a[3]), "r"(b0), "r"(b1));
}
__device__ __forceinline__ unsigned bf2pack(float a, float b) {
    __nv_bfloat16 x = __float2bfloat16(a), y = __float2bfloat16(b);
    return (unsigned)__bfloat16_as_ushort(x) | ((unsigned)__bfloat16_as_ushort(y) << 16);
}

// ---------------- device scratch ----------------
__device__ float g_gx[(size_t)SS * BB * G4];
__device__ __align__(16) __nv_bfloat16 g_whi[NCTA][32 * 256];  // [cta][row][k-half]
__device__ __align__(16) __nv_bfloat16 g_wlo[NCTA][32 * 256];
__device__ __align__(16) __nv_bfloat16 g_xhi[(size_t)BB * SS * II];
__device__ __align__(16) __nv_bfloat16 g_xlo[(size_t)BB * SS * II];
__device__ __align__(16) __nv_bfloat16 g_wxthi[G4 * II];
__device__ __align__(16) __nv_bfloat16 g_wxtlo[G4 * II];
__device__ __align__(16) __nv_bfloat16 g_h[2][2][BB * HH];
__device__ float g_hfin[BB * HH];
__device__ float g_part[NGRP][2][32 * 64];        // pair partials, parity-buffered
__device__ unsigned g_flags[NGRP * FLAG_PAD];     // h-publish flags (even CTAs)
__device__ unsigned g_pflags[NGRP * FLAG_PAD];    // partial-ready flags (odd CTAs)

// ---------------- init ----------------
__global__ void __launch_bounds__(256) init_kernel() {
    int t = blockIdx.x * 256 + threadIdx.x;
    if (t < 32768) ((uint4*)g_h)[t] = make_uint4(0,0,0,0);
    if (t < NGRP * FLAG_PAD) { g_flags[t] = 0u; g_pflags[t] = 0u; }
}

// ---------------- recurrent W prep: per-(group,parity) k-half tiles -------
__global__ void __launch_bounds__(256) prepw_kernel(
    const float* __restrict__ Wf, const float* __restrict__ Wi,
    const float* __restrict__ Wc, const float* __restrict__ Wo)
{
    int gid = blockIdx.x * 256 + threadIdx.x;    // 2048*256 = 524288
    int cta = gid >> 12;          // 4096 threads per cta (8192 elems)
    int rem = gid & 4095;
    int r   = rem >> 7;           // 0..31
    int kp  = rem & 127;
    int k0  = kp * 2;
    int g = r >> 3, l = r & 7, j = (cta >> 1) * 8 + l;
    int kbase = II + (cta & 1) * 256;
    const float* W = (g==0)?Wf:(g==1)?Wi:(g==2)?Wc:Wo;
    #pragma unroll
    for (int q = 0; q < 2; q++) {
        int k = k0 + q;
        float w = W[(size_t)(kbase + k) * HH + j];
        __nv_bfloat16 hi = __float2bfloat16(w);
        __nv_bfloat16 lo = __float2bfloat16(w - __bfloat162float(hi));
        g_whi[cta][r * 256 + k] = hi;
        g_wlo[cta][r * 256 + k] = lo;
    }
}

// ---------------- x split (R12, passed) ----------------
__global__ void __launch_bounds__(256) prepx_kernel(const float* __restrict__ x) {
    size_t gid = (size_t)blockIdx.x * 256 + threadIdx.x;
    float4 v = *(const float4*)&x[gid * 4];
    __nv_bfloat16 h0 = __float2bfloat16(v.x), h1 = __float2bfloat16(v.y);
    __nv_bfloat16 h2 = __float2bfloat16(v.z), h3 = __float2bfloat16(v.w);
    uint2 hw, lw;
    hw.x = (unsigned)__bfloat16_as_ushort(h0) | ((unsigned)__bfloat16_as_ushort(h1) << 16);
    hw.y = (unsigned)__bfloat16_as_ushort(h2) | ((unsigned)__bfloat16_as_ushort(h3) << 16);
    lw.x = bf2pack(v.x - __bfloat162float(h0), v.y - __bfloat162float(h1));
    lw.y = bf2pack(v.z - __bfloat162float(h2), v.w - __bfloat162float(h3));
    ((uint2*)g_xhi)[gid] = hw;
    ((uint2*)g_xlo)[gid] = lw;
}

// ---------------- Wx transpose+split (R12, passed) ----------------
__global__ void __launch_bounds__(256) prepwx_kernel(
    const float* __restrict__ Wf, const float* __restrict__ Wi,
    const float* __restrict__ Wc, const float* __restrict__ Wo)
{
    int gid = blockIdx.x * 256 + threadIdx.x;
    int col = gid >> 7;
    int kp  = gid & 127;
    int g = col >> 9, j = col & 511;
    const float* W = (g==0)?Wf:(g==1)?Wi:(g==2)?Wc:Wo;
    #pragma unroll
    for (int q = 0; q < 2; q++) {
        int k = kp * 2 + q;
        float w = W[(size_t)k * HH + j];
        __nv_bfloat16 hi = __float2bfloat16(w);
        g_wxthi[col * II + k] = hi;
        g_wxtlo[col * II + k] = __float2bfloat16(w - __bfloat162float(hi));
    }
}

// ---------------- precompute v2 (R12, passed, verbatim) -------------------
__global__ void __launch_bounds__(256) precompute2_kernel(
    const float* __restrict__ bf, const float* __restrict__ bi,
    const float* __restrict__ bc, const float* __restrict__ bo)
{
    extern __shared__ __align__(16) unsigned char sm[];
    const int ct = blockIdx.x;
    const int st = blockIdx.y;
    const int b  = blockIdx.z;
    const int t = threadIdx.x, lane = t & 31, wid = t >> 5;
    const int g8 = lane >> 2, t4 = lane & 3;
    const int mg = wid & 1, ngp = (wid >> 1) & 1, kg = wid >> 2;

    {
        const uint4* xh = (const uint4*)&g_xhi[((size_t)b * SS + st * 64) * II];
        const uint4* xl = (const uint4*)&g_xlo[((size_t)b * SS + st * 64) * II];
        const uint4* wh = (const uint4*)&g_wxthi[(ct * 64) * II];
        const uint4* wl = (const uint4*)&g_wxtlo[(ct * 64) * II];
        #pragma unroll
        for (int i = 0; i < 8; i++) {
            int ch = i * 256 + t;
            int r = ch >> 5, cc = ch & 31;
            unsigned dst = (unsigned)(r * XPITCH + cc * 16);
            *(uint4*)(sm + PC_A_HI + dst) = __ldg(xh + ch);
            *(uint4*)(sm + PC_A_LO + dst) = __ldg(xl + ch);
            *(uint4*)(sm + PC_B_HI + dst) = __ldg(wh + ch);
            *(uint4*)(sm + PC_B_LO + dst) = __ldg(wl + ch);
        }
    }
    __syncthreads();

    const unsigned a_lr = (unsigned)((lane & 15) * XPITCH + ((lane & 16) ? 16 : 0));
    const unsigned ahi0 = smem_u32(sm + PC_A_HI) + a_lr
                        + (unsigned)(mg * 32 * XPITCH + kg * 256);
    const unsigned ahi1 = ahi0 + 16u * XPITCH;
    const unsigned alo0 = ahi0 + (PC_A_LO - PC_A_HI);
    const unsigned alo1 = alo0 + 16u * XPITCH;
    const int brow = ((lane & 16) >> 1) + (lane & 7);
    const unsigned b_lr = (unsigned)(brow * XPITCH + ((lane & 8) ? 16 : 0));
    const unsigned bhi0 = smem_u32(sm + PC_B_HI) + b_lr
                        + (unsigned)(ngp * 32 * XPITCH + kg * 256);
    const unsigned bhi1 = bhi0 + 16u * XPITCH;
    const unsigned blo0 = bhi0 + (PC_B_LO - PC_B_HI);
    const unsigned blo1 = blo0 + 16u * XPITCH;

    float acc[2][4][4] = {};
    #pragma unroll
    for (int kk = 0; kk < 8; kk++) {
        const unsigned ko = (unsigned)(kk * 32);
        unsigned ah0[4], ah1[4], al0[4], al1[4], bh0[4], bh1[4], bl0[4], bl1[4];
        ldsm4(ah0, ahi0 + ko); ldsm4(ah1, ahi1 + ko);
        ldsm4(al0, alo0 + ko); ldsm4(al1, alo1 + ko);
        ldsm4(bh0, bhi0 + ko); ldsm4(bh1, bhi1 + ko);
        ldsm4(bl0, blo0 + ko); ldsm4(bl1, blo1 + ko);
        #pragma unroll
        for (int mi = 0; mi < 2; mi++) {
            const unsigned* ah = mi ? ah1 : ah0;
            const unsigned* al = mi ? al1 : al0;
            #pragma unroll
            for (int nb = 0; nb < 4; nb++) {
                const unsigned* bh = (nb < 2) ? bh0 : bh1;
                const unsigned* bl = (nb < 2) ? bl0 : bl1;
                const int ix = (nb & 1) * 2;
                mma16816(acc[mi][nb], ah, bh[ix], bh[ix + 1]);
                mma16816(acc[mi][nb], ah, bl[ix], bl[ix + 1]);
                mma16816(acc[mi][nb], al, bh[ix], bh[ix + 1]);
            }
        }
    }
    __syncthreads();

    float* rb = (float*)sm;
    #pragma unroll
    for (int mi = 0; mi < 2; mi++) {
        #pragma unroll
        for (int nb = 0; nb < 4; nb++) {
            int row = mg * 32 + mi * 16 + g8;
            int col = ngp * 32 + nb * 8 + 2 * t4;
            *(float2*)&rb[kg * RSLAB + row * RP + col]
                = make_float2(acc[mi][nb][0], acc[mi][nb][1]);
            *(float2*)&rb[kg * RSLAB + (row + 8) * RP + col]
                = make_float2(acc[mi][nb][2], acc[mi][nb][3]);
        }
    }
    __syncthreads();

    {
        const int g = ct >> 3;
        const float* bias = (g==0)?bf:(g==1)?bi:(g==2)?bc:bo;
        const int j0 = (ct & 7) * 64;
        const int r = t >> 2, cb = (t & 3) * 16;
        float* dst = &g_gx[((size_t)(st * 64 + r) * BB + b) * G4 + ct * 64 + cb];
        #pragma unroll
        for (int v4 = 0; v4 < 4; v4++) {
            float4 v;
            float* o = (float*)&v;
            #pragma unroll
            for (int q = 0; q < 4; q++) {
                int col = cb + v4 * 4 + q;
                o[q] = rb[r * RP + col] + rb[RSLAB + r * RP + col] + bias[j0 + col];
            }
            *(float4*)&dst[v4 * 4] = v;
        }
    }
}

// ---------------- persistent step kernel: k-split CTA pairs ---------------
// CTA c: grp = c>>1 (M=32 gate rows, h cols grp*8..+7), kp_half = c&1
// (k in [256*kp_half, +256)). 8 warps = 2n x 4kwg, warp tile m32 x n32 x k64.
// Odd CTA ships its summed partial to even via g_part + release flag.
__global__ void __launch_bounds__(256, 1) step_kernel() {
    extern __shared__ __align__(16) unsigned char sm[];
    const int cta = blockIdx.x, t = threadIdx.x;
    const int grp = cta >> 1, kph = cta & 1;
    const int wid = t >> 5, lane = t & 31;
    const int g8 = lane >> 2, t4 = lane & 3;
    const int ng = wid & 1, kwg = wid >> 1;
    const int n0 = ng * 32;

    // W k-half tiles -> smem once (1024 uint4 each)
    {
        const uint4* shi = (const uint4*)g_whi[cta];
        const uint4* slo = (const uint4*)g_wlo[cta];
        #pragma unroll
        for (int i = 0; i < 4; i++) {
            int ch = i * 256 + t;
            int r = ch >> 5, cc = ch & 31;
            *(uint4*)(sm + SM_WHI + r * XPITCH + cc * 16) = shi[ch];
            *(uint4*)(sm + SM_WLO + r * XPITCH + cc * 16) = slo[ch];
        }
    }
    __syncthreads();

    const unsigned a_lr = (unsigned)((lane & 15) * XPITCH + ((lane & 16) ? 16 : 0));
    const unsigned ahi0 = smem_u32(sm + SM_WHI) + a_lr + (unsigned)(kwg * 128);
    const unsigned ahi1 = ahi0 + 16u * XPITCH;
    const unsigned alo0 = ahi0 + (SM_WLO - SM_WHI);
    const unsigned alo1 = alo0 + 16u * XPITCH;
    const int brow = ((lane & 16) >> 1) + (lane & 7);
    const unsigned b_lr = (unsigned)(brow * XPITCH + ((lane & 8) ? 16 : 0));
    const unsigned bhi0 = smem_u32(sm + SM_HHI) + (unsigned)(n0 * XPITCH) + b_lr + (unsigned)(kwg * 128);
    const unsigned bhi1 = bhi0 + 16u * XPITCH;
    const unsigned blo0 = bhi0 + (SM_HLO - SM_HHI);
    const unsigned blo1 = blo0 + 16u * XPITCH;

    const int ub = t >> 2, lp = (t & 3) * 2;
    float c_reg[2] = {};
    float* gb = (float*)(sm + SM_HHI);

    for (int s = 0; s < SS; s++) {
        const int par = s & 1;

        // stage own k-half of h (per-warp quadrant): 8 i-iters x (hi+lo)
        {
            const uint4* hs0 = (const uint4*)g_h[par][0];
            const uint4* hs1 = (const uint4*)g_h[par][1];
            #pragma unroll
            for (int i = 0; i < 8; i++) {
                int e = i * 32 + lane;
                int rr = e >> 3, cc = e & 7;
                int src = (n0 + rr) * 64 + kph * 32 + kwg * 8 + cc;
                unsigned dst = (unsigned)((n0 + rr) * XPITCH + kwg * 128 + cc * 16);
                *(uint4*)(sm + SM_HHI + dst) = __ldcg(hs0 + src);
                *(uint4*)(sm + SM_HLO + dst) = __ldcg(hs1 + src);
            }
        }
        float2 gx[4];
        if (kph == 0) {
            const float* p = &g_gx[((size_t)s * BB + ub) * G4 + grp * 8 + lp];
            #pragma unroll
            for (int g = 0; g < 4; g++) gx[g] = *(const float2*)&p[g * 512];
        }
        __syncwarp();

        // GEMM: 4 k-steps x (8 LDSM.x4 + 24 MMA)
        float acc[2][4][4] = {};
        #pragma unroll
        for (int kk = 0; kk < 4; kk++) {
            const unsigned ko = (unsigned)(kk * 32);
            unsigned ah0[4], ah1[4], al0[4], al1[4], bh0[4], bh1[4], bl0[4], bl1[4];
            ldsm4(ah0, ahi0 + ko); ldsm4(ah1, ahi1 + ko);
            ldsm4(al0, alo0 + ko); ldsm4(al1, alo1 + ko);
            ldsm4(bh0, bhi0 + ko); ldsm4(bh1, bhi1 + ko);
            ldsm4(bl0, blo0 + ko); ldsm4(bl1, blo1 + ko);
            #pragma unroll
            for (int mi = 0; mi < 2; mi++) {
                const unsigned* ah = mi ? ah1 : ah0;
                const unsigned* al = mi ? al1 : al0;
                #pragma unroll
                for (int nb = 0; nb < 4; nb++) {
                    const unsigned* bh = (nb < 2) ? bh0 : bh1;
                    const unsigned* bl = (nb < 2) ? bl0 : bl1;
                    const int ix = (nb & 1) * 2;
                    mma16816(acc[mi][nb], ah, bh[ix], bh[ix + 1]);
                    mma16816(acc[mi][nb], ah, bl[ix], bl[ix + 1]);
                    mma16816(acc[mi][nb], al, bh[ix], bh[ix + 1]);
                }
            }
        }
        __syncthreads();   // all LDSM done -> gbuf may overwrite h-hi

        // spill warp partials: gbuf[kwg*32 + row][batch]
        #pragma unroll
        for (int mi = 0; mi < 2; mi++) {
            #pragma unroll
            for (int nb = 0; nb < 4; nb++) {
                int row = kwg * 32 + mi * 16 + g8;
                int col = n0 + nb * 8 + 2 * t4;
                *(float2*)&gb[row * GBP + col]       = make_float2(acc[mi][nb][0], acc[mi][nb][1]);
                *(float2*)&gb[(row + 8) * GBP + col] = make_float2(acc[mi][nb][2], acc[mi][nb][3]);
            }
        }
        __syncthreads();

        // sum the 4 in-CTA k-partials for this thread's 2 cells x 4 gates
        float sums[2][4];
        #pragma unroll
        for (int q = 0; q < 2; q++) {
            int l = lp + q;
            #pragma unroll
            for (int g = 0; g < 4; g++) {
                float v = 0.f;
                #pragma unroll
                for (int k = 0; k < 4; k++)
                    v += gb[(k * 32 + g * 8 + l) * GBP + ub];
                sums[q][g] = v;
            }
        }

        if (kph == 1) {
            // ---- odd: publish partial to even partner ----
            float* dst = g_part[grp][par];
            #pragma unroll
            for (int q = 0; q < 2; q++)
                #pragma unroll
                for (int g = 0; g < 4; g++)
                    __stcg(&dst[(g * 8 + lp + q) * 64 + ub], sums[q][g]);
            __syncthreads();
            if (t == 0) {
                __threadfence();
                asm volatile("st.release.gpu.u32 [%0], %1;"
                             :: "l"(&g_pflags[grp * FLAG_PAD]), "r"((unsigned)(s + 1))
                             : "memory");
            }
        } else {
            // ---- even: merge partner partial, gates, publish h ----
            if (t == 0) {
                unsigned v;
                const unsigned* fp = &g_pflags[grp * FLAG_PAD];
                asm volatile("ld.acquire.gpu.u32 %0, [%1];" : "=r"(v) : "l"(fp) : "memory");
                while (v < (unsigned)(s + 1)) {
                    asm volatile("nanosleep.u32 32;");
                    asm volatile("ld.acquire.gpu.u32 %0, [%1];" : "=r"(v) : "l"(fp) : "memory");
                }
            }
            __syncthreads();
            const float* src = g_part[grp][par];
            float hv[2];
            #pragma unroll
            for (int q = 0; q < 2; q++) {
                int l = lp + q;
                float gs[4];
                #pragma unroll
                for (int g = 0; g < 4; g++)
                    gs[g] = sums[q][g] + __ldcg(&src[(g * 8 + l) * 64 + ub]);
                float gf = gs[0] + ((q == 0) ? gx[0].x : gx[0].y);
                float gi = gs[1] + ((q == 0) ? gx[1].x : gx[1].y);
                float gu = gs[2] + ((q == 0) ? gx[2].x : gx[2].y);
                float go = gs[3] + ((q == 0) ? gx[3].x : gx[3].y);
                float f = fsigmoid(gf), ii = fsigmoid(gi);
                float u = ftanh(gu),    o = fsigmoid(go);
                c_reg[q] = f * c_reg[q] + ii * u;
                hv[q] = o * ftanh(c_reg[q]);
            }
            __nv_bfloat16 h0 = __float2bfloat16(hv[0]);
            __nv_bfloat16 h1 = __float2bfloat16(hv[1]);
            unsigned hiw = (unsigned)__bfloat16_as_ushort(h0) | ((unsigned)__bfloat16_as_ushort(h1) << 16);
            unsigned low = bf2pack(hv[0] - __bfloat162float(h0), hv[1] - __bfloat162float(h1));
            const int j0 = grp * 8 + lp;
            *(unsigned*)&g_h[1 - par][0][ub * HH + j0] = hiw;
            *(unsigned*)&g_h[1 - par][1][ub * HH + j0] = low;
            if (s == SS - 1) {
                g_hfin[ub * HH + j0]     = hv[0];
                g_hfin[ub * HH + j0 + 1] = hv[1];
            }
            __syncthreads();
            if (t == 0) {
                __threadfence();
                asm volatile("st.release.gpu.u32 [%0], %1;"
                             :: "l"(&g_flags[grp * FLAG_PAD]), "r"((unsigned)(s + 1))
                             : "memory");
            }
        }

        // ---- global wait: 64 even-CTA flags, warp-0 spin with backoff ----
        if (t < 32) {
            #pragma unroll
            for (int half = 0; half < 2; half++) {
                const unsigned* fp = &g_flags[(t + half * 32) * FLAG_PAD];
                unsigned v;
                asm volatile("ld.acquire.gpu.u32 %0, [%1];" : "=r"(v) : "l"(fp) : "memory");
                while (v < (unsigned)(s + 1)) {
                    asm volatile("nanosleep.u32 64;");
                    asm volatile("ld.acquire.gpu.u32 %0, [%1];" : "=r"(v) : "l"(fp) : "memory");
                }
            }
        }
        __syncthreads();
    }
}

// ---------------- output head ----------------
__global__ void __launch_bounds__(256) out_kernel(
    const float* __restrict__ Wout, const float* __restrict__ bout,
    float* __restrict__ out)
{
    __shared__ float hsh[HH];
    const int b = blockIdx.x, j = threadIdx.x;
    for (int k = j; k < HH; k += 256) hsh[k] = g_hfin[b * HH + k];
    __syncthreads();
    float a0 = 0.f, a1 = 0.f, a2 = 0.f, a3 = 0.f;
    #pragma unroll 4
    for (int k = 0; k < HH; k += 4) {
        a0 += hsh[k+0] * Wout[(size_t)(k+0)*OO + j];
        a1 += hsh[k+1] * Wout[(size_t)(k+1)*OO + j];
        a2 += hsh[k+2] * Wout[(size_t)(k+2)*OO + j];
        a3 += hsh[k+3] * Wout[(size_t)(k+3)*OO + j];
    }
    out[(size_t)b * OO + j] = a0 + a1 + a2 + a3 + bout[j];
}

// ---------------- launcher ----------------
extern "C" void kernel_launch(void* const* d_in, const int* in_sizes, int n_in,
                              void* d_out, int out_size)
{
    (void)in_sizes; (void)n_in; (void)out_size;
    const float* x    = (const float*)d_in[0];
    const float* Wf   = (const float*)d_in[1];
    const float* bf   = (const float*)d_in[2];
    const float* Wi   = (const float*)d_in[3];
    const float* bi   = (const float*)d_in[4];
    const float* Wc   = (const float*)d_in[5];
    const float* bc   = (const float*)d_in[6];
    const float* Wo   = (const float*)d_in[7];
    const float* bo   = (const float*)d_in[8];
    const float* Wout = (const float*)d_in[9];
    const float* bout = (const float*)d_in[10];
    float* out = (float*)d_out;

    cudaFuncSetAttribute(step_kernel,
                         cudaFuncAttributeMaxDynamicSharedMemorySize, SM_TOTAL);
    cudaFuncSetAttribute(precompute2_kernel,
                         cudaFuncAttributeMaxDynamicSharedMemorySize, PC_TOTAL);

    init_kernel<<<128, 256>>>();
    prepw_kernel<<<2048, 256>>>(Wf, Wi, Wc, Wo);
    prepx_kernel<<<16384, 256>>>(x);
    prepwx_kernel<<<1024, 256>>>(Wf, Wi, Wc, Wo);
    precompute2_kernel<<<dim3(32, 16, BB), 256, PC_TOTAL>>>(bf, bi, bc, bo);
    step_kernel<<<NCTA, 256, SM_TOTAL>>>();
    out_kernel<<<BB, 256>>>(Wout, bout, out);
}